// round 8
// baseline (speedup 1.0000x reference)
#include <cuda_runtime.h>
#include <cuda_bf16.h>
#include <cstdint>

#define N_NODES 50000
#define N_EDGES 500000
#define HDIM    128
#define H2      256
#define NLAYERS 4
#define NGRAPH  1000
#define MEPS    1e-7f
#define LNEPS   1e-5f
#define SCAN_BLKS 49

// ---------------- scratch ----------------------------------------------------
__device__ __align__(256) float g_h[(size_t)N_NODES * HDIM];
__device__ __align__(256) float g_z[(size_t)N_NODES * HDIM];
__device__ __align__(256) float g_o[(size_t)N_NODES * HDIM];
__device__ __align__(256) float g_u[(size_t)N_NODES * H2];
__device__ __align__(256) float g_y[(size_t)N_NODES * HDIM];   // pure y from FFMA gemm2
__device__ __align__(256) float g_tv[(size_t)N_NODES * HDIM];  // pure y from mma gemm2
__device__ __align__(256) __nv_bfloat16 g_ah[(size_t)N_NODES * HDIM];
__device__ __align__(256) __nv_bfloat16 g_al[(size_t)N_NODES * HDIM];
__device__ __align__(256) __nv_bfloat16 g_uh[(size_t)N_NODES * H2];
__device__ __align__(256) __nv_bfloat16 g_ul[(size_t)N_NODES * H2];
__device__ __align__(256) __nv_bfloat16 g_tuh[(size_t)N_NODES * H2];
__device__ __align__(256) __nv_bfloat16 g_tul[(size_t)N_NODES * H2];
__device__ __align__(256) __nv_bfloat16 g_w1h[NLAYERS * H2 * HDIM]; // [l][n][k]
__device__ __align__(256) __nv_bfloat16 g_w1l[NLAYERS * H2 * HDIM];
__device__ __align__(256) __nv_bfloat16 g_w2h[NLAYERS * HDIM * H2]; // [l][n][k]
__device__ __align__(256) __nv_bfloat16 g_w2l[NLAYERS * HDIM * H2];
__device__ int    g_cnt[N_NODES + 1];
__device__ int    g_ptr[N_NODES + 1];
__device__ int    g_cur[N_NODES];
__device__ int    g_ssrc[N_EDGES];
__device__ float4 g_sattr[N_EDGES];
__device__ int    g_gcnt[NGRAPH + 1];
__device__ int    g_gptr[NGRAPH + 1];
__device__ int    g_bsum[64];
__device__ int    g_boff[64];
__device__ int    g_flag[2];

// ---------------- helpers -----------------------------------------------------
__device__ __forceinline__ uint32_t s2u(const void* p) {
    uint32_t a;
    asm("{ .reg .u64 t; cvta.to.shared.u64 t, %1; cvt.u32.u64 %0, t; }" : "=r"(a) : "l"(p));
    return a;
}
__device__ __forceinline__ uint32_t lds32(uint32_t a) {
    uint32_t v;
    asm volatile("ld.shared.b32 %0, [%1];" : "=r"(v) : "r"(a));
    return v;
}
__device__ __forceinline__ void mma16816(float* d, const uint32_t* a, const uint32_t* b) {
    asm volatile(
        "mma.sync.aligned.m16n8k16.row.col.f32.bf16.bf16.f32 "
        "{%0,%1,%2,%3}, {%4,%5,%6,%7}, {%8,%9}, {%0,%1,%2,%3};"
        : "+f"(d[0]), "+f"(d[1]), "+f"(d[2]), "+f"(d[3])
        : "r"(a[0]), "r"(a[1]), "r"(a[2]), "r"(a[3]), "r"(b[0]), "r"(b[1]));
}
__device__ __forceinline__ unsigned long long fma2(unsigned long long a,
                                                   unsigned long long b,
                                                   unsigned long long c) {
    unsigned long long d;
    asm("fma.rn.f32x2 %0, %1, %2, %3;" : "=l"(d) : "l"(a), "l"(b), "l"(c));
    return d;
}
__device__ __forceinline__ unsigned long long dup2(float a) {
    unsigned long long d;
    asm("mov.b64 %0, {%1, %1};" : "=l"(d) : "f"(a));
    return d;
}
__device__ __forceinline__ float2 unpack2(unsigned long long v) {
    float2 r;
    asm("mov.b64 {%0, %1}, %2;" : "=f"(r.x), "=f"(r.y) : "l"(v));
    return r;
}

// ---------------- prep -------------------------------------------------------
__global__ void k_zero() {
    int i = blockIdx.x * blockDim.x + threadIdx.x;
    if (i <= N_NODES) g_cnt[i] = 0;
    if (i <= NGRAPH) g_gcnt[i] = 0;
    if (i < 2) g_flag[i] = 0;
}
__global__ void k_hist_dst(const int* __restrict__ ei) {
    int e = blockIdx.x * blockDim.x + threadIdx.x;
    if (e < N_EDGES) atomicAdd(&g_cnt[ei[N_EDGES + e]], 1);
}
__global__ void k_hist_batch(const int* __restrict__ batch) {
    int i = blockIdx.x * blockDim.x + threadIdx.x;
    if (i < N_NODES) atomicAdd(&g_gcnt[batch[i]], 1);
}
__device__ __forceinline__ int blk_scan(int v, int* ws) {
    int lane = threadIdx.x & 31, w = threadIdx.x >> 5;
    int val = v;
#pragma unroll
    for (int o = 1; o < 32; o <<= 1) { int u = __shfl_up_sync(0xffffffffu, val, o); if (lane >= o) val += u; }
    if (lane == 31) ws[w] = val;
    __syncthreads();
    if (w == 0) {
        int s = ws[lane];
#pragma unroll
        for (int o = 1; o < 32; o <<= 1) { int u = __shfl_up_sync(0xffffffffu, s, o); if (lane >= o) s += u; }
        ws[lane] = s;
    }
    __syncthreads();
    return val + (w ? ws[w - 1] : 0);   // inclusive
}
__global__ void k_scan1() {
    __shared__ int ws[32];
    int i = blockIdx.x * 1024 + threadIdx.x;
    int v = (i < N_NODES) ? g_cnt[i] : 0;
    int incl = blk_scan(v, ws);
    if (i < N_NODES) g_ptr[i] = incl - v;
    if (threadIdx.x == 1023) g_bsum[blockIdx.x] = incl;
}
__global__ void k_scan2() {
    __shared__ int ws[32];
    int t = threadIdx.x;
    int v = (t < SCAN_BLKS) ? g_bsum[t] : 0;
    int incl = blk_scan(v, ws);
    if (t < SCAN_BLKS) g_boff[t] = incl - v;
    __syncthreads();
    int gv = (t < NGRAPH) ? g_gcnt[t] : 0;
    int gincl = blk_scan(gv, ws);
    if (t < NGRAPH) g_gptr[t] = gincl - gv;
    if (t == 0) g_gptr[NGRAPH] = N_NODES;
}
__global__ void k_scan3() {
    int i = blockIdx.x * 1024 + threadIdx.x;
    if (i < N_NODES) {
        int p = g_ptr[i] + g_boff[blockIdx.x];
        g_ptr[i] = p;
        g_cur[i] = p;
    }
    if (i == 0) g_ptr[N_NODES] = N_EDGES;
}
__global__ void k_scatter(const int* __restrict__ ei, const float* __restrict__ ea) {
    int e = blockIdx.x * blockDim.x + threadIdx.x;
    if (e >= N_EDGES) return;
    int d = ei[N_EDGES + e];
    int pos = atomicAdd(&g_cur[d], 1);
    g_ssrc[pos] = ei[e];
    g_sattr[pos] = make_float4(ea[3 * e], ea[3 * e + 1], ea[3 * e + 2], 0.f);
}
// weights -> [l][n][k] split-bf16
__global__ void k_convw(const float* __restrict__ W1, const float* __restrict__ W2) {
    int i = blockIdx.x * blockDim.x + threadIdx.x;
    const int tot = NLAYERS * H2 * HDIM;
    if (i >= tot) return;
    {
        int l = i / (H2 * HDIM), rem = i % (H2 * HDIM);
        int n = rem / HDIM, k = rem % HDIM;
        float w = W1[(size_t)l * HDIM * H2 + (size_t)k * H2 + n];
        __nv_bfloat16 hi = __float2bfloat16(w);
        g_w1h[i] = hi;
        g_w1l[i] = __float2bfloat16(w - __bfloat162float(hi));
    }
    {
        int l = i / (HDIM * H2), rem = i % (HDIM * H2);
        int n = rem / H2, k = rem % H2;
        float w = W2[(size_t)l * H2 * HDIM + (size_t)k * HDIM + n];
        __nv_bfloat16 hi = __float2bfloat16(w);
        g_w2h[i] = hi;
        g_w2l[i] = __float2bfloat16(w - __bfloat162float(hi));
    }
}

// ---------------- node encoder -----------------------------------------------
__global__ void k_encode(const float* __restrict__ x, const float* __restrict__ W,
                         const float* __restrict__ b) {
    __shared__ float4 sW[9][32];
    __shared__ float4 sb[32];
    int tid = threadIdx.x;
    for (int i = tid; i < 9 * 32; i += blockDim.x)
        sW[i / 32][i % 32] = *(const float4*)&W[(i / 32) * HDIM + (i % 32) * 4];
    if (tid < 32) sb[tid] = *(const float4*)&b[tid * 4];
    __syncthreads();
    int gw = (blockIdx.x * blockDim.x + tid) >> 5;
    if (gw >= N_NODES) return;
    int lane = tid & 31;
    const float* xr = x + gw * 9;
    float xv[9];
#pragma unroll
    for (int k = 0; k < 9; k++) xv[k] = __ldg(&xr[k]);
    float4 acc = sb[lane];
#pragma unroll
    for (int k = 0; k < 9; k++) {
        float4 w = sW[k][lane];
        acc.x += xv[k] * w.x; acc.y += xv[k] * w.y;
        acc.z += xv[k] * w.z; acc.w += xv[k] * w.w;
    }
    ((float4*)g_h)[gw * 32 + lane] = acc;
}

// ---------------- LN(h)*g+b, relu -> g_z --------------------------------------
__global__ void k_lnrelu(const float* __restrict__ g, const float* __restrict__ b) {
    int gw = (blockIdx.x * blockDim.x + threadIdx.x) >> 5;
    if (gw >= N_NODES) return;
    int lane = threadIdx.x & 31;
    float4 v = ((const float4*)g_h)[gw * 32 + lane];
    float s = v.x + v.y + v.z + v.w;
#pragma unroll
    for (int o = 16; o > 0; o >>= 1) s += __shfl_xor_sync(0xffffffffu, s, o);
    float mean = s * (1.f / 128.f);
    float4 d = make_float4(v.x - mean, v.y - mean, v.z - mean, v.w - mean);
    float q = d.x * d.x + d.y * d.y + d.z * d.z + d.w * d.w;
#pragma unroll
    for (int o = 16; o > 0; o >>= 1) q += __shfl_xor_sync(0xffffffffu, q, o);
    float rstd = rsqrtf(q * (1.f / 128.f) + LNEPS);
    float4 gg = __ldg((const float4*)&g[lane * 4]);
    float4 bb = __ldg((const float4*)&b[lane * 4]);
    float4 o4;
    o4.x = fmaxf(d.x * rstd * gg.x + bb.x, 0.f);
    o4.y = fmaxf(d.y * rstd * gg.y + bb.y, 0.f);
    o4.z = fmaxf(d.z * rstd * gg.z + bb.z, 0.f);
    o4.w = fmaxf(d.w * rstd * gg.w + bb.w, 0.f);
    ((float4*)g_z)[gw * 32 + lane] = o4;
}

// ---------------- edge softmax-agg: writes g_o float + split-bf16 -------------
__global__ void __launch_bounds__(256) k_edge(const float* __restrict__ eW,
                                              const float* __restrict__ eb,
                                              const float* __restrict__ tall,
                                              int layer, int use_z) {
    __shared__ float4 sw[4][32];
    int tid = threadIdx.x;
    if (tid < 32) {
        sw[0][tid] = *(const float4*)&eW[0 * HDIM + tid * 4];
        sw[1][tid] = *(const float4*)&eW[1 * HDIM + tid * 4];
        sw[2][tid] = *(const float4*)&eW[2 * HDIM + tid * 4];
        sw[3][tid] = *(const float4*)&eb[tid * 4];
    }
    __syncthreads();
    int gw = (blockIdx.x * blockDim.x + tid) >> 5;
    if (gw >= N_NODES) return;
    int lane = tid & 31;
    const float4* zp = (const float4*)(use_z ? g_z : g_h);
    float tv = __ldg(&tall[layer]);
    int j0 = __ldg(&g_ptr[gw]), j1 = __ldg(&g_ptr[gw + 1]);
    float4 w0 = sw[0][lane], w1 = sw[1][lane], w2 = sw[2][lane], wb = sw[3][lane];
    float4 den = make_float4(0.f, 0.f, 0.f, 0.f);
    float4 num = make_float4(0.f, 0.f, 0.f, 0.f);
    for (int j = j0; j < j1; j++) {
        int s = __ldg(&g_ssrc[j]);
        float4 a = __ldg(&g_sattr[j]);
        float4 hv = __ldg(&zp[s * 32 + lane]);
        float m, e;
        m = fmaxf(hv.x + wb.x + a.x * w0.x + a.y * w1.x + a.z * w2.x, 0.f) + MEPS;
        e = __expf(tv * m); den.x += e; num.x += e * m;
        m = fmaxf(hv.y + wb.y + a.x * w0.y + a.y * w1.y + a.z * w2.y, 0.f) + MEPS;
        e = __expf(tv * m); den.y += e; num.y += e * m;
        m = fmaxf(hv.z + wb.z + a.x * w0.z + a.y * w1.z + a.z * w2.z, 0.f) + MEPS;
        e = __expf(tv * m); den.z += e; num.z += e * m;
        m = fmaxf(hv.w + wb.w + a.x * w0.w + a.y * w1.w + a.z * w2.w, 0.f) + MEPS;
        e = __expf(tv * m); den.w += e; num.w += e * m;
    }
    float4 hz = zp[gw * 32 + lane];
    float4 o;
    if (j1 > j0) {
        o.x = num.x / den.x + hz.x;
        o.y = num.y / den.y + hz.y;
        o.z = num.z / den.z + hz.z;
        o.w = num.w / den.w + hz.w;
    } else {
        o = hz;
    }
    ((float4*)g_o)[gw * 32 + lane] = o;
    union { __nv_bfloat16 b[4]; uint2 u; } ch, cl;
    ch.b[0] = __float2bfloat16(o.x); ch.b[1] = __float2bfloat16(o.y);
    ch.b[2] = __float2bfloat16(o.z); ch.b[3] = __float2bfloat16(o.w);
    cl.b[0] = __float2bfloat16(o.x - __bfloat162float(ch.b[0]));
    cl.b[1] = __float2bfloat16(o.y - __bfloat162float(ch.b[1]));
    cl.b[2] = __float2bfloat16(o.z - __bfloat162float(ch.b[2]));
    cl.b[3] = __float2bfloat16(o.w - __bfloat162float(ch.b[3]));
    ((uint2*)g_ah)[gw * 32 + lane] = ch.u;
    ((uint2*)g_al)[gw * 32 + lane] = cl.u;
}

// ---------------- FFMA GEMM1 (proven in R1) -----------------------------------
__global__ void __launch_bounds__(256) k_gemm1(const float* __restrict__ B,
                                               const float* __restrict__ bias,
                                               const float* __restrict__ lg,
                                               const float* __restrict__ lb) {
    __shared__ float As[8][65];
    __shared__ float Bs[8][256];
    const float* A = g_o;
    int tid = threadIdx.x;
    int tx = tid & 31, ty = tid >> 5;
    int row0 = blockIdx.x * 64;
    unsigned long long acc[8][4];
#pragma unroll
    for (int i = 0; i < 8; i++)
#pragma unroll
        for (int j = 0; j < 4; j++) acc[i][j] = 0ull;

    for (int kk = 0; kk < HDIM; kk += 8) {
#pragma unroll
        for (int l = 0; l < 2; l++) {
            int e = tid + l * 256;
            int k = e & 7, m = e >> 3;
            int r = row0 + m;
            As[k][m] = (r < N_NODES) ? A[r * HDIM + kk + k] : 0.f;
        }
#pragma unroll
        for (int l = 0; l < 2; l++) {
            int q = tid + l * 256;
            int k = q >> 6, n4 = q & 63;
            *(float4*)&Bs[k][n4 * 4] = __ldg((const float4*)&B[(kk + k) * H2 + n4 * 4]);
        }
        __syncthreads();
#pragma unroll
        for (int k = 0; k < 8; k++) {
            unsigned long long bv[4];
            bv[0] = *(const unsigned long long*)&Bs[k][tx * 4];
            bv[1] = *(const unsigned long long*)&Bs[k][tx * 4 + 2];
            bv[2] = *(const unsigned long long*)&Bs[k][128 + tx * 4];
            bv[3] = *(const unsigned long long*)&Bs[k][128 + tx * 4 + 2];
#pragma unroll
            for (int i = 0; i < 8; i++) {
                unsigned long long a2 = dup2(As[k][ty * 8 + i]);
#pragma unroll
                for (int j = 0; j < 4; j++) acc[i][j] = fma2(a2, bv[j], acc[i][j]);
            }
        }
        __syncthreads();
    }
    float4 bia0 = __ldg((const float4*)&bias[tx * 4]);
    float4 bia1 = __ldg((const float4*)&bias[128 + tx * 4]);
    float4 gv0 = __ldg((const float4*)&lg[tx * 4]);
    float4 gv1 = __ldg((const float4*)&lg[128 + tx * 4]);
    float4 bv0 = __ldg((const float4*)&lb[tx * 4]);
    float4 bv1 = __ldg((const float4*)&lb[128 + tx * 4]);
#pragma unroll
    for (int i = 0; i < 8; i++) {
        float v[8];
        float2 p;
        p = unpack2(acc[i][0]); v[0] = p.x + bia0.x; v[1] = p.y + bia0.y;
        p = unpack2(acc[i][1]); v[2] = p.x + bia0.z; v[3] = p.y + bia0.w;
        p = unpack2(acc[i][2]); v[4] = p.x + bia1.x; v[5] = p.y + bia1.y;
        p = unpack2(acc[i][3]); v[6] = p.x + bia1.z; v[7] = p.y + bia1.w;
        float s = 0.f;
#pragma unroll
        for (int j = 0; j < 8; j++) s += v[j];
#pragma unroll
        for (int o = 16; o > 0; o >>= 1) s += __shfl_xor_sync(0xffffffffu, s, o);
        float mean = s * (1.f / 256.f);
        float q = 0.f;
#pragma unroll
        for (int j = 0; j < 8; j++) { float d = v[j] - mean; q += d * d; }
#pragma unroll
        for (int o = 16; o > 0; o >>= 1) q += __shfl_xor_sync(0xffffffffu, q, o);
        float rstd = rsqrtf(q * (1.f / 256.f) + LNEPS);
        int r = row0 + ty * 8 + i;
        if (r < N_NODES) {
            float4 o0, o1;
            o0.x = fmaxf((v[0] - mean) * rstd * gv0.x + bv0.x, 0.f);
            o0.y = fmaxf((v[1] - mean) * rstd * gv0.y + bv0.y, 0.f);
            o0.z = fmaxf((v[2] - mean) * rstd * gv0.z + bv0.z, 0.f);
            o0.w = fmaxf((v[3] - mean) * rstd * gv0.w + bv0.w, 0.f);
            o1.x = fmaxf((v[4] - mean) * rstd * gv1.x + bv1.x, 0.f);
            o1.y = fmaxf((v[5] - mean) * rstd * gv1.y + bv1.y, 0.f);
            o1.z = fmaxf((v[6] - mean) * rstd * gv1.z + bv1.z, 0.f);
            o1.w = fmaxf((v[7] - mean) * rstd * gv1.w + bv1.w, 0.f);
            *(float4*)&g_u[(size_t)r * H2 + tx * 4] = o0;
            *(float4*)&g_u[(size_t)r * H2 + 128 + tx * 4] = o1;
        }
    }
}

// ---------------- FFMA GEMM2 (proven in R1) + g_y store -----------------------
__global__ void __launch_bounds__(256) k_gemm2(const float* __restrict__ B,
                                               const float* __restrict__ bias,
                                               int first) {
    __shared__ float As[8][129];
    __shared__ float Bs[8][128];
    const float* A = g_u;
    int tid = threadIdx.x;
    int tx = tid & 15, ty = tid >> 4;
    int row0 = blockIdx.x * 128;
    unsigned long long acc[8][4];
#pragma unroll
    for (int i = 0; i < 8; i++)
#pragma unroll
        for (int j = 0; j < 4; j++) acc[i][j] = 0ull;

    for (int kk = 0; kk < H2; kk += 8) {
        {
            int m = tid >> 1, k0 = (tid & 1) * 4;
            int r = row0 + m;
            float4 av = (r < N_NODES) ? __ldg((const float4*)&A[(size_t)r * H2 + kk + k0])
                                      : make_float4(0.f, 0.f, 0.f, 0.f);
            As[k0 + 0][m] = av.x; As[k0 + 1][m] = av.y;
            As[k0 + 2][m] = av.z; As[k0 + 3][m] = av.w;
        }
        {
            int k = tid >> 5, n4 = tid & 31;
            *(float4*)&Bs[k][n4 * 4] = __ldg((const float4*)&B[(kk + k) * HDIM + n4 * 4]);
        }
        __syncthreads();
#pragma unroll
        for (int k = 0; k < 8; k++) {
            unsigned long long bv[4];
            bv[0] = *(const unsigned long long*)&Bs[k][tx * 4];
            bv[1] = *(const unsigned long long*)&Bs[k][tx * 4 + 2];
            bv[2] = *(const unsigned long long*)&Bs[k][64 + tx * 4];
            bv[3] = *(const unsigned long long*)&Bs[k][64 + tx * 4 + 2];
#pragma unroll
            for (int i = 0; i < 8; i++) {
                unsigned long long a2 = dup2(As[k][ty * 8 + i]);
#pragma unroll
                for (int j = 0; j < 4; j++) acc[i][j] = fma2(a2, bv[j], acc[i][j]);
            }
        }
        __syncthreads();
    }
    float4 bia0 = __ldg((const float4*)&bias[tx * 4]);
    float4 bia1 = __ldg((const float4*)&bias[64 + tx * 4]);
#pragma unroll
    for (int i = 0; i < 8; i++) {
        int r = row0 + ty * 8 + i;
        if (r < N_NODES) {
            float2 p;
            float4 y0, y1;
            p = unpack2(acc[i][0]); y0.x = p.x + bia0.x; y0.y = p.y + bia0.y;
            p = unpack2(acc[i][1]); y0.z = p.x + bia0.z; y0.w = p.y + bia0.w;
            p = unpack2(acc[i][2]); y1.x = p.x + bia1.x; y1.y = p.y + bia1.y;
            p = unpack2(acc[i][3]); y1.z = p.x + bia1.z; y1.w = p.y + bia1.w;
            *(float4*)&g_y[(size_t)r * HDIM + tx * 4] = y0;
            *(float4*)&g_y[(size_t)r * HDIM + 64 + tx * 4] = y1;
            float* hp = &g_h[(size_t)r * HDIM];
            if (first) {
                *(float4*)&hp[tx * 4] = y0;
                *(float4*)&hp[64 + tx * 4] = y1;
            } else {
                float4 h0 = *(float4*)&hp[tx * 4];
                float4 h1 = *(float4*)&hp[64 + tx * 4];
                h0.x += y0.x; h0.y += y0.y; h0.z += y0.z; h0.w += y0.w;
                h1.x += y1.x; h1.y += y1.y; h1.z += y1.z; h1.w += y1.w;
                *(float4*)&hp[tx * 4] = h0;
                *(float4*)&hp[64 + tx * 4] = h1;
            }
        }
    }
}

// ---------------- mma test kernels (diagnostic only) --------------------------
__device__ __forceinline__ void ld_tile16(uint32_t dst, const __nv_bfloat16* __restrict__ src,
                                          int rows, int rowstride, int k0, int row0, int maxrow) {
    for (int idx = threadIdx.x; idx < rows * 2; idx += 256) {
        int r = idx >> 1, sb = idx & 1;
        uint4 v = make_uint4(0u, 0u, 0u, 0u);
        int gr = row0 + r;
        if (gr < maxrow) v = *(const uint4*)(src + (size_t)gr * rowstride + k0 + sb * 8);
        asm volatile("st.shared.v4.b32 [%0], {%1, %2, %3, %4};"
                     :: "r"(dst + (uint32_t)(r * 48 + sb * 16)), "r"(v.x), "r"(v.y), "r"(v.z), "r"(v.w));
    }
}
__device__ __forceinline__ void ldfragA(uint32_t* a, uint32_t base, int row, int kb) {
    uint32_t p = base + (uint32_t)(row * 48 + kb * 2);
    a[0] = lds32(p);
    a[1] = lds32(p + 384u);
    a[2] = lds32(p + 16u);
    a[3] = lds32(p + 400u);
}
__device__ __forceinline__ void ldfragB(uint32_t* b, uint32_t base, int n, int kb) {
    uint32_t p = base + (uint32_t)(n * 48 + kb * 2);
    b[0] = lds32(p);
    b[1] = lds32(p + 16u);
}

#define G1_SMEM 35840
__global__ void __launch_bounds__(256) k_mma1t(const __nv_bfloat16* __restrict__ Bh,
                                               const __nv_bfloat16* __restrict__ Bl,
                                               const float* __restrict__ bias,
                                               const float* __restrict__ lg,
                                               const float* __restrict__ lb) {
    extern __shared__ char dsm[];
    uint32_t smA = s2u(dsm);
    uint32_t smAl = smA + 3072u, smB = smA + 6144u, smBl = smA + 18432u;
    float* spar = (float*)(dsm + 30720);
    float* sred = (float*)(dsm + 33792);
    int tid = threadIdx.x, wid = tid >> 5, lane = tid & 31;
    int mwarp = wid >> 2, nwarp = wid & 3;
    int gr = lane >> 2, kp = (lane & 3) * 2;
    int row0 = blockIdx.x * 64;

    spar[tid] = __ldg(&bias[tid]);
    spar[256 + tid] = __ldg(&lg[tid]);
    spar[512 + tid] = __ldg(&lb[tid]);

    float acc[2][8][4];
#pragma unroll
    for (int i = 0; i < 2; i++)
#pragma unroll
        for (int j = 0; j < 8; j++)
#pragma unroll
            for (int c = 0; c < 4; c++) acc[i][j][c] = 0.f;

    for (int kk = 0; kk < HDIM; kk += 16) {
        if (kk) __syncthreads();
        ld_tile16(smA,  g_ah, 64, HDIM, kk, row0, N_NODES);
        ld_tile16(smAl, g_al, 64, HDIM, kk, row0, N_NODES);
        ld_tile16(smB,  Bh, 256, HDIM, kk, 0, 1 << 30);
        ld_tile16(smBl, Bl, 256, HDIM, kk, 0, 1 << 30);
        __syncthreads();
        uint32_t ah[2][4], al[2][4];
#pragma unroll
        for (int mt = 0; mt < 2; mt++) {
            int row = mwarp * 32 + mt * 16 + gr;
            ldfragA(ah[mt], smA,  row, kp);
            ldfragA(al[mt], smAl, row, kp);
        }
#pragma unroll
        for (int nt = 0; nt < 8; nt++) {
            int n = nwarp * 64 + nt * 8 + gr;
            uint32_t bh[2], bl[2];
            ldfragB(bh, smB,  n, kp);
            ldfragB(bl, smBl, n, kp);
#pragma unroll
            for (int mt = 0; mt < 2; mt++) {
                mma16816(acc[mt][nt], ah[mt], bh);
                mma16816(acc[mt][nt], al[mt], bh);
                mma16816(acc[mt][nt], ah[mt], bl);
            }
        }
    }
    __syncthreads();
#pragma unroll
    for (int mt = 0; mt < 2; mt++) {
        float s0 = 0.f, q0 = 0.f, s1 = 0.f, q1 = 0.f;
#pragma unroll
        for (int nt = 0; nt < 8; nt++) {
            int n = nwarp * 64 + nt * 8 + kp;
            float b0 = spar[n], b1 = spar[n + 1];
            float* c = acc[mt][nt];
            c[0] += b0; c[1] += b1; c[2] += b0; c[3] += b1;
            s0 += c[0] + c[1]; q0 += c[0] * c[0] + c[1] * c[1];
            s1 += c[2] + c[3]; q1 += c[2] * c[2] + c[3] * c[3];
        }
#pragma unroll
        for (int o = 1; o < 4; o <<= 1) {
            s0 += __shfl_xor_sync(0xffffffffu, s0, o);
            q0 += __shfl_xor_sync(0xffffffffu, q0, o);
            s1 += __shfl_xor_sync(0xffffffffu, s1, o);
            q1 += __shfl_xor_sync(0xffffffffu, q1, o);
        }
        if ((lane & 3) == 0) {
            int r = mwarp * 32 + mt * 16 + gr;
            sred[nwarp * 64 + r] = s0;       sred[256 + nwarp * 64 + r] = q0;
            sred[nwarp * 64 + r + 8] = s1;   sred[256 + nwarp * 64 + r + 8] = q1;
        }
    }
    __syncthreads();
#pragma unroll
    for (int mt = 0; mt < 2; mt++) {
#pragma unroll
        for (int hf = 0; hf < 2; hf++) {
            int rl = mwarp * 32 + mt * 16 + gr + hf * 8;
            int row = row0 + rl;
            float s = sred[rl] + sred[64 + rl] + sred[128 + rl] + sred[192 + rl];
            float q = sred[256 + rl] + sred[320 + rl] + sred[384 + rl] + sred[448 + rl];
            float mean = s * (1.f / 256.f);
            float var = q * (1.f / 256.f) - mean * mean;
            float rstd = rsqrtf(fmaxf(var, 0.f) + LNEPS);
            if (row < N_NODES) {
#pragma unroll
                for (int nt = 0; nt < 8; nt++) {
                    int n = nwarp * 64 + nt * 8 + kp;
                    float v0 = acc[mt][nt][hf * 2 + 0];
                    float v1 = acc[mt][nt][hf * 2 + 1];
                    float u0 = fmaxf((v0 - mean) * rstd * spar[256 + n] + spar[512 + n], 0.f);
                    float u1 = fmaxf((v1 - mean) * rstd * spar[257 + n] + spar[513 + n], 0.f);
                    __nv_bfloat16 h0 = __float2bfloat16(u0), h1 = __float2bfloat16(u1);
                    union { __nv_bfloat16 b[2]; uint32_t u; } ph, pl;
                    ph.b[0] = h0; ph.b[1] = h1;
                    pl.b[0] = __float2bfloat16(u0 - __bfloat162float(h0));
                    pl.b[1] = __float2bfloat16(u1 - __bfloat162float(h1));
                    size_t off = (size_t)row * H2 + n;
                    *(uint32_t*)&g_tuh[off] = ph.u;
                    *(uint32_t*)&g_tul[off] = pl.u;
                }
            }
        }
    }
}

#define G2_SMEM 18944
__global__ void __launch_bounds__(256) k_mma2t(const __nv_bfloat16* __restrict__ Bh,
                                               const __nv_bfloat16* __restrict__ Bl,
                                               const float* __restrict__ bias) {
    extern __shared__ char dsm[];
    uint32_t smA = s2u(dsm);
    uint32_t smAl = smA + 3072u, smB = smA + 6144u, smBl = smA + 12288u;
    float* spar = (float*)(dsm + 18432);
    int tid = threadIdx.x, wid = tid >> 5, lane = tid & 31;
    int mwarp = wid >> 2, nwarp = wid & 3;
    int gr = lane >> 2, kp = (lane & 3) * 2;
    int row0 = blockIdx.x * 64;

    if (tid < 128) spar[tid] = __ldg(&bias[tid]);

    float acc[2][4][4];
#pragma unroll
    for (int i = 0; i < 2; i++)
#pragma unroll
        for (int j = 0; j < 4; j++)
#pragma unroll
            for (int c = 0; c < 4; c++) acc[i][j][c] = 0.f;

    for (int kk = 0; kk < H2; kk += 16) {
        if (kk) __syncthreads();
        ld_tile16(smA,  g_uh, 64, H2, kk, row0, N_NODES);
        ld_tile16(smAl, g_ul, 64, H2, kk, row0, N_NODES);
        ld_tile16(smB,  Bh, 128, H2, kk, 0, 1 << 30);
        ld_tile16(smBl, Bl, 128, H2, kk, 0, 1 << 30);
        __syncthreads();
        uint32_t ah[2][4], al[2][4];
#pragma unroll
        for (int mt = 0; mt < 2; mt++) {
            int row = mwarp * 32 + mt * 16 + gr;
            ldfragA(ah[mt], smA,  row, kp);
            ldfragA(al[mt], smAl, row, kp);
        }
#pragma unroll
        for (int nt = 0; nt < 4; nt++) {
            int n = nwarp * 32 + nt * 8 + gr;
            uint32_t bh[2], bl[2];
            ldfragB(bh, smB,  n, kp);
            ldfragB(bl, smBl, n, kp);
#pragma unroll
            for (int mt = 0; mt < 2; mt++) {
                mma16816(acc[mt][nt], ah[mt], bh);
                mma16816(acc[mt][nt], al[mt], bh);
                mma16816(acc[mt][nt], ah[mt], bl);
            }
        }
    }
    __syncthreads();
#pragma unroll
    for (int mt = 0; mt < 2; mt++)
#pragma unroll
        for (int hf = 0; hf < 2; hf++) {
            int row = row0 + mwarp * 32 + mt * 16 + gr + hf * 8;
            if (row < N_NODES) {
#pragma unroll
                for (int nt = 0; nt < 4; nt++) {
                    int n = nwarp * 32 + nt * 8 + kp;
                    float y0 = acc[mt][nt][hf * 2 + 0] + spar[n];
                    float y1 = acc[mt][nt][hf * 2 + 1] + spar[n + 1];
                    *(float2*)&g_tv[(size_t)row * HDIM + n] = make_float2(y0, y1);
                }
            }
        }
}

// split g_u float into bf16 hi/lo for the GEMM2 test
__global__ void k_split_u() {
    int i = blockIdx.x * blockDim.x + threadIdx.x;
    if (i >= N_NODES * H2) return;
    float v = g_u[i];
    __nv_bfloat16 hi = __float2bfloat16(v);
    g_uh[i] = hi;
    g_ul[i] = __float2bfloat16(v - __bfloat162float(hi));
}
__global__ void k_cmp1() {
    int i = blockIdx.x * blockDim.x + threadIdx.x;
    if (i >= N_NODES * H2) return;
    float recon = __bfloat162float(g_tuh[i]) + __bfloat162float(g_tul[i]);
    float ref = g_u[i];
    float d = fabsf(recon - ref);
    if (!(d <= 1e-2f * (fabsf(ref) + 0.1f))) atomicAdd(&g_flag[0], 1);
}
__global__ void k_cmp2() {
    int i = blockIdx.x * blockDim.x + threadIdx.x;
    if (i >= N_NODES * HDIM) return;
    float d = fabsf(g_tv[i] - g_y[i]);
    if (!(d <= 1e-2f * (fabsf(g_y[i]) + 0.1f))) atomicAdd(&g_flag[1], 1);
}
// duration-encoded diagnosis: +~3.3ms if GEMM1 test failed, +~13ms if GEMM2 failed
__global__ void k_spin() {
    if (threadIdx.x != 0 || blockIdx.x != 0) return;
    long long n = (g_flag[0] > 0 ? 1500000LL : 0) + (g_flag[1] > 0 ? 6000000LL : 0);
    float x = 1.0f;
    for (long long i = 0; i < n; i++) x = fmaf(x, 1.0000001f, 1e-9f);
    if (x == 12345.678f) g_h[0] = x;   // never true; defeats DCE
}

// ---------------- mean pool ---------------------------------------------------
__global__ void k_pool(float* __restrict__ out) {
    int g = blockIdx.x, c = threadIdx.x;
    int s = g_gptr[g], e = g_gptr[g + 1];
    float acc = 0.f;
    for (int i = s; i < e; i++) acc += g_z[(size_t)i * HDIM + c];
    out[g * HDIM + c] = (e > s) ? acc / (float)(e - s) : 0.f;
}

// ---------------- launch ------------------------------------------------------
extern "C" void kernel_launch(void* const* d_in, const int* in_sizes, int n_in,
                              void* d_out, int out_size) {
    (void)in_sizes; (void)n_in; (void)out_size;
    const float* x     = (const float*)d_in[0];
    const int*   ei    = (const int*)d_in[1];
    const float* eattr = (const float*)d_in[2];
    const int*   batch = (const int*)d_in[3];
    const float* encW  = (const float*)d_in[4];
    const float* encb  = (const float*)d_in[5];
    const float* eW    = (const float*)d_in[6];
    const float* eb    = (const float*)d_in[7];
    const float* lng   = (const float*)d_in[8];
    const float* lnb   = (const float*)d_in[9];
    const float* W1    = (const float*)d_in[10];
    const float* b1    = (const float*)d_in[11];
    const float* mg    = (const float*)d_in[12];
    const float* mb    = (const float*)d_in[13];
    const float* W2    = (const float*)d_in[14];
    const float* b2    = (const float*)d_in[15];
    const float* tptr  = (const float*)d_in[16];
    float* out = (float*)d_out;

    const int NWBLK = (N_NODES * 32 + 255) / 256;
    const int NT64 = (N_NODES + 63) / 64;

    k_zero<<<(N_NODES + 256) / 256, 256>>>();
    k_hist_dst<<<(N_EDGES + 255) / 256, 256>>>(ei);
    k_hist_batch<<<(N_NODES + 255) / 256, 256>>>(batch);
    k_scan1<<<SCAN_BLKS, 1024>>>();
    k_scan2<<<1, 1024>>>();
    k_scan3<<<SCAN_BLKS, 1024>>>();
    k_scatter<<<(N_EDGES + 255) / 256, 256>>>(ei, eattr);
    k_convw<<<(NLAYERS * H2 * HDIM + 255) / 256, 256>>>(W1, W2);

    k_encode<<<NWBLK, 256>>>(x, encW, encb);

    for (int i = 0; i < NLAYERS; i++) {
        if (i > 0) k_lnrelu<<<NWBLK, 256>>>(lng + (size_t)i * HDIM, lnb + (size_t)i * HDIM);
        k_edge<<<NWBLK, 256>>>(eW, eb, tptr, i, (i > 0) ? 1 : 0);
        k_gemm1<<<NT64, 256>>>(W1 + (size_t)i * HDIM * H2,
                               b1 + (size_t)i * H2,
                               mg + (size_t)i * H2,
                               mb + (size_t)i * H2);
        k_gemm2<<<(N_NODES + 127) / 128, 256>>>(W2 + (size_t)i * H2 * HDIM,
                                                b2 + (size_t)i * HDIM,
                                                (i == 0) ? 1 : 0);
        if (i == 0) {
            // diagnostic: mma recomputation of layer-0 GEMMs vs FFMA results
            k_split_u<<<(N_NODES * H2 + 255) / 256, 256>>>();
            k_mma1t<<<NT64, 256, G1_SMEM>>>(g_w1h, g_w1l, b1, mg, mb);
            k_cmp1<<<(N_NODES * H2 + 255) / 256, 256>>>();
            k_mma2t<<<NT64, 256, G2_SMEM>>>(g_w2h, g_w2l, b2);
            k_cmp2<<<(N_NODES * HDIM + 255) / 256, 256>>>();
        }
    }

    k_lnrelu<<<NWBLK, 256>>>(lng, lnb);
    k_pool<<<NGRAPH, HDIM>>>(out);
    k_spin<<<1, 32>>>();
}

// round 11
// speedup vs baseline: 17.9907x; 17.9907x over previous
#include <cuda_runtime.h>
#include <cuda_bf16.h>
#include <cstdint>

#define N_NODES 50000
#define N_EDGES 500000
#define HDIM    128
#define H2      256
#define NLAYERS 4
#define NGRAPH  1000
#define MEPS    1e-7f
#define LNEPS   1e-5f
#define SCAN_BLKS 49

// ---------------- scratch (device globals; no runtime allocation) ----------
__device__ float  g_h[(size_t)N_NODES * HDIM];
__device__ float  g_z[(size_t)N_NODES * HDIM];
__device__ float  g_o[(size_t)N_NODES * HDIM];
__device__ float  g_u[(size_t)N_NODES * H2];
__device__ int    g_cnt[N_NODES + 1];
__device__ int    g_ptr[N_NODES + 1];
__device__ int    g_cur[N_NODES];
__device__ int    g_ssrc[N_EDGES];
__device__ float4 g_sattr[N_EDGES];
__device__ int    g_gcnt[NGRAPH + 1];
__device__ int    g_gptr[NGRAPH + 1];
__device__ int    g_bsum[64];
__device__ int    g_boff[64];

// ---------------- f32x2 packed FMA helpers ---------------------------------
__device__ __forceinline__ unsigned long long fma2(unsigned long long a,
                                                   unsigned long long b,
                                                   unsigned long long c) {
    unsigned long long d;
    asm("fma.rn.f32x2 %0, %1, %2, %3;" : "=l"(d) : "l"(a), "l"(b), "l"(c));
    return d;
}
__device__ __forceinline__ unsigned long long dup2(float a) {
    unsigned long long d;
    asm("mov.b64 %0, {%1, %1};" : "=l"(d) : "f"(a));
    return d;
}
__device__ __forceinline__ float2 unpack2(unsigned long long v) {
    float2 r;
    asm("mov.b64 {%0, %1}, %2;" : "=f"(r.x), "=f"(r.y) : "l"(v));
    return r;
}

// ---------------- prep kernels ----------------------------------------------
__global__ void k_zero() {
    int i = blockIdx.x * blockDim.x + threadIdx.x;
    if (i <= N_NODES) g_cnt[i] = 0;
    if (i <= NGRAPH) g_gcnt[i] = 0;
}

__global__ void k_hist_dst(const int* __restrict__ ei) {
    int e = blockIdx.x * blockDim.x + threadIdx.x;
    if (e < N_EDGES) atomicAdd(&g_cnt[ei[N_EDGES + e]], 1);
}

__global__ void k_hist_batch(const int* __restrict__ batch) {
    int i = blockIdx.x * blockDim.x + threadIdx.x;
    if (i < N_NODES) atomicAdd(&g_gcnt[batch[i]], 1);
}

// multi-block scan (validated in R8 profile: 4.9us vs 73us single-block)
__device__ __forceinline__ int blk_scan(int v, int* ws) {
    int lane = threadIdx.x & 31, w = threadIdx.x >> 5;
    int val = v;
#pragma unroll
    for (int o = 1; o < 32; o <<= 1) { int u = __shfl_up_sync(0xffffffffu, val, o); if (lane >= o) val += u; }
    if (lane == 31) ws[w] = val;
    __syncthreads();
    if (w == 0) {
        int s = ws[lane];
#pragma unroll
        for (int o = 1; o < 32; o <<= 1) { int u = __shfl_up_sync(0xffffffffu, s, o); if (lane >= o) s += u; }
        ws[lane] = s;
    }
    __syncthreads();
    return val + (w ? ws[w - 1] : 0);   // inclusive
}
__global__ void k_scan1() {
    __shared__ int ws[32];
    int i = blockIdx.x * 1024 + threadIdx.x;
    int v = (i < N_NODES) ? g_cnt[i] : 0;
    int incl = blk_scan(v, ws);
    if (i < N_NODES) g_ptr[i] = incl - v;
    if (threadIdx.x == 1023) g_bsum[blockIdx.x] = incl;
}
__global__ void k_scan2() {
    __shared__ int ws[32];
    int t = threadIdx.x;
    int v = (t < SCAN_BLKS) ? g_bsum[t] : 0;
    int incl = blk_scan(v, ws);
    if (t < SCAN_BLKS) g_boff[t] = incl - v;
    __syncthreads();
    int gv = (t < NGRAPH) ? g_gcnt[t] : 0;
    int gincl = blk_scan(gv, ws);
    if (t < NGRAPH) g_gptr[t] = gincl - gv;
    if (t == 0) g_gptr[NGRAPH] = N_NODES;
}
__global__ void k_scan3() {
    int i = blockIdx.x * 1024 + threadIdx.x;
    if (i < N_NODES) {
        int p = g_ptr[i] + g_boff[blockIdx.x];
        g_ptr[i] = p;
        g_cur[i] = p;
    }
    if (i == 0) g_ptr[N_NODES] = N_EDGES;
}

__global__ void k_scatter(const int* __restrict__ ei, const float* __restrict__ ea) {
    int e = blockIdx.x * blockDim.x + threadIdx.x;
    if (e >= N_EDGES) return;
    int d = ei[N_EDGES + e];
    int pos = atomicAdd(&g_cur[d], 1);
    g_ssrc[pos] = ei[e];
    g_sattr[pos] = make_float4(ea[3 * e], ea[3 * e + 1], ea[3 * e + 2], 0.f);
}

// ---------------- node encoder: h = x @ Wn + bn ------------------------------
__global__ void k_encode(const float* __restrict__ x, const float* __restrict__ W,
                         const float* __restrict__ b) {
    __shared__ float4 sW[9][32];
    __shared__ float4 sb[32];
    int tid = threadIdx.x;
    for (int i = tid; i < 9 * 32; i += blockDim.x)
        sW[i / 32][i % 32] = *(const float4*)&W[(i / 32) * HDIM + (i % 32) * 4];
    if (tid < 32) sb[tid] = *(const float4*)&b[tid * 4];
    __syncthreads();
    int gw = (blockIdx.x * blockDim.x + tid) >> 5;
    if (gw >= N_NODES) return;
    int lane = tid & 31;
    const float* xr = x + gw * 9;
    float xv[9];
#pragma unroll
    for (int k = 0; k < 9; k++) xv[k] = __ldg(&xr[k]);
    float4 acc = sb[lane];
#pragma unroll
    for (int k = 0; k < 9; k++) {
        float4 w = sW[k][lane];
        acc.x += xv[k] * w.x; acc.y += xv[k] * w.y;
        acc.z += xv[k] * w.z; acc.w += xv[k] * w.w;
    }
    ((float4*)g_h)[gw * 32 + lane] = acc;
}

// ---------------- LN(h)*g+b then relu -> g_z ---------------------------------
__global__ void k_lnrelu(const float* __restrict__ g, const float* __restrict__ b) {
    int gw = (blockIdx.x * blockDim.x + threadIdx.x) >> 5;
    if (gw >= N_NODES) return;
    int lane = threadIdx.x & 31;
    float4 v = ((const float4*)g_h)[gw * 32 + lane];
    float s = v.x + v.y + v.z + v.w;
#pragma unroll
    for (int o = 16; o > 0; o >>= 1) s += __shfl_xor_sync(0xffffffffu, s, o);
    float mean = s * (1.f / 128.f);
    float4 d = make_float4(v.x - mean, v.y - mean, v.z - mean, v.w - mean);
    float q = d.x * d.x + d.y * d.y + d.z * d.z + d.w * d.w;
#pragma unroll
    for (int o = 16; o > 0; o >>= 1) q += __shfl_xor_sync(0xffffffffu, q, o);
    float rstd = rsqrtf(q * (1.f / 128.f) + LNEPS);
    float4 gg = __ldg((const float4*)&g[lane * 4]);
    float4 bb = __ldg((const float4*)&b[lane * 4]);
    float4 o4;
    o4.x = fmaxf(d.x * rstd * gg.x + bb.x, 0.f);
    o4.y = fmaxf(d.y * rstd * gg.y + bb.y, 0.f);
    o4.z = fmaxf(d.z * rstd * gg.z + bb.z, 0.f);
    o4.w = fmaxf(d.w * rstd * gg.w + bb.w, 0.f);
    ((float4*)g_z)[gw * 32 + lane] = o4;
}

// ---------------- fused edge softmax-aggregation (warp per node) -------------
__global__ void __launch_bounds__(256) k_edge(const float* __restrict__ eW,
                                              const float* __restrict__ eb,
                                              const float* __restrict__ tall,
                                              int layer, int use_z) {
    __shared__ float4 sw[4][32];
    int tid = threadIdx.x;
    if (tid < 32) {
        sw[0][tid] = *(const float4*)&eW[0 * HDIM + tid * 4];
        sw[1][tid] = *(const float4*)&eW[1 * HDIM + tid * 4];
        sw[2][tid] = *(const float4*)&eW[2 * HDIM + tid * 4];
        sw[3][tid] = *(const float4*)&eb[tid * 4];
    }
    __syncthreads();
    int gw = (blockIdx.x * blockDim.x + tid) >> 5;
    if (gw >= N_NODES) return;
    int lane = tid & 31;
    const float4* zp = (const float4*)(use_z ? g_z : g_h);
    float tv = __ldg(&tall[layer]);
    int j0 = __ldg(&g_ptr[gw]), j1 = __ldg(&g_ptr[gw + 1]);
    float4 w0 = sw[0][lane], w1 = sw[1][lane], w2 = sw[2][lane], wb = sw[3][lane];
    float4 den = make_float4(0.f, 0.f, 0.f, 0.f);
    float4 num = make_float4(0.f, 0.f, 0.f, 0.f);
    for (int j = j0; j < j1; j++) {
        int s = __ldg(&g_ssrc[j]);
        float4 a = __ldg(&g_sattr[j]);
        float4 hv = __ldg(&zp[s * 32 + lane]);
        float m, e;
        m = fmaxf(hv.x + wb.x + a.x * w0.x + a.y * w1.x + a.z * w2.x, 0.f) + MEPS;
        e = __expf(tv * m); den.x += e; num.x += e * m;
        m = fmaxf(hv.y + wb.y + a.x * w0.y + a.y * w1.y + a.z * w2.y, 0.f) + MEPS;
        e = __expf(tv * m); den.y += e; num.y += e * m;
        m = fmaxf(hv.z + wb.z + a.x * w0.z + a.y * w1.z + a.z * w2.z, 0.f) + MEPS;
        e = __expf(tv * m); den.z += e; num.z += e * m;
        m = fmaxf(hv.w + wb.w + a.x * w0.w + a.y * w1.w + a.z * w2.w, 0.f) + MEPS;
        e = __expf(tv * m); den.w += e; num.w += e * m;
    }
    float4 hz = zp[gw * 32 + lane];
    float4 o;
    if (j1 > j0) {
        o.x = num.x / den.x + hz.x;
        o.y = num.y / den.y + hz.y;
        o.z = num.z / den.z + hz.z;
        o.w = num.w / den.w + hz.w;
    } else {
        o = hz;
    }
    ((float4*)g_o)[gw * 32 + lane] = o;
}

// ---------------- GEMM1: u = relu(LN(g_o @ W1 + b1)) -------------------------
// BM=64, BN=256(full row -> LN fused), BK=8, 256 thr, 8x8/thread, f32x2 FMA.
__global__ void __launch_bounds__(256) k_gemm1(const float* __restrict__ B,
                                               const float* __restrict__ bias,
                                               const float* __restrict__ lg,
                                               const float* __restrict__ lb) {
    __shared__ float As[8][65];
    __shared__ float Bs[8][256];
    const float* A = g_o;
    int tid = threadIdx.x;
    int tx = tid & 31, ty = tid >> 5;
    int row0 = blockIdx.x * 64;
    unsigned long long acc[8][4];
#pragma unroll
    for (int i = 0; i < 8; i++)
#pragma unroll
        for (int j = 0; j < 4; j++) acc[i][j] = 0ull;

    for (int kk = 0; kk < HDIM; kk += 8) {
#pragma unroll
        for (int l = 0; l < 2; l++) {
            int e = tid + l * 256;
            int k = e & 7, m = e >> 3;
            int r = row0 + m;
            As[k][m] = (r < N_NODES) ? A[r * HDIM + kk + k] : 0.f;
        }
#pragma unroll
        for (int l = 0; l < 2; l++) {
            int q = tid + l * 256;
            int k = q >> 6, n4 = q & 63;
            *(float4*)&Bs[k][n4 * 4] = __ldg((const float4*)&B[(kk + k) * H2 + n4 * 4]);
        }
        __syncthreads();
#pragma unroll
        for (int k = 0; k < 8; k++) {
            unsigned long long bv[4];
            bv[0] = *(const unsigned long long*)&Bs[k][tx * 4];
            bv[1] = *(const unsigned long long*)&Bs[k][tx * 4 + 2];
            bv[2] = *(const unsigned long long*)&Bs[k][128 + tx * 4];
            bv[3] = *(const unsigned long long*)&Bs[k][128 + tx * 4 + 2];
#pragma unroll
            for (int i = 0; i < 8; i++) {
                unsigned long long a2 = dup2(As[k][ty * 8 + i]);
#pragma unroll
                for (int j = 0; j < 4; j++) acc[i][j] = fma2(a2, bv[j], acc[i][j]);
            }
        }
        __syncthreads();
    }
    float4 bia0 = __ldg((const float4*)&bias[tx * 4]);
    float4 bia1 = __ldg((const float4*)&bias[128 + tx * 4]);
    float4 gv0 = __ldg((const float4*)&lg[tx * 4]);
    float4 gv1 = __ldg((const float4*)&lg[128 + tx * 4]);
    float4 bv0 = __ldg((const float4*)&lb[tx * 4]);
    float4 bv1 = __ldg((const float4*)&lb[128 + tx * 4]);
#pragma unroll
    for (int i = 0; i < 8; i++) {
        float v[8];
        float2 p;
        p = unpack2(acc[i][0]); v[0] = p.x + bia0.x; v[1] = p.y + bia0.y;
        p = unpack2(acc[i][1]); v[2] = p.x + bia0.z; v[3] = p.y + bia0.w;
        p = unpack2(acc[i][2]); v[4] = p.x + bia1.x; v[5] = p.y + bia1.y;
        p = unpack2(acc[i][3]); v[6] = p.x + bia1.z; v[7] = p.y + bia1.w;
        float s = 0.f;
#pragma unroll
        for (int j = 0; j < 8; j++) s += v[j];
#pragma unroll
        for (int o = 16; o > 0; o >>= 1) s += __shfl_xor_sync(0xffffffffu, s, o);
        float mean = s * (1.f / 256.f);
        float q = 0.f;
#pragma unroll
        for (int j = 0; j < 8; j++) { float d = v[j] - mean; q += d * d; }
#pragma unroll
        for (int o = 16; o > 0; o >>= 1) q += __shfl_xor_sync(0xffffffffu, q, o);
        float rstd = rsqrtf(q * (1.f / 256.f) + LNEPS);
        int r = row0 + ty * 8 + i;
        if (r < N_NODES) {
            float4 o0, o1;
            o0.x = fmaxf((v[0] - mean) * rstd * gv0.x + bv0.x, 0.f);
            o0.y = fmaxf((v[1] - mean) * rstd * gv0.y + bv0.y, 0.f);
            o0.z = fmaxf((v[2] - mean) * rstd * gv0.z + bv0.z, 0.f);
            o0.w = fmaxf((v[3] - mean) * rstd * gv0.w + bv0.w, 0.f);
            o1.x = fmaxf((v[4] - mean) * rstd * gv1.x + bv1.x, 0.f);
            o1.y = fmaxf((v[5] - mean) * rstd * gv1.y + bv1.y, 0.f);
            o1.z = fmaxf((v[6] - mean) * rstd * gv1.z + bv1.z, 0.f);
            o1.w = fmaxf((v[7] - mean) * rstd * gv1.w + bv1.w, 0.f);
            *(float4*)&g_u[(size_t)r * H2 + tx * 4] = o0;
            *(float4*)&g_u[(size_t)r * H2 + 128 + tx * 4] = o1;
        }
    }
}

// ---------------- GEMM2: h (+)= g_u @ W2 + b2 --------------------------------
// BM=128, BN=128, BK=8, 256 thr, 8x8/thread, f32x2 FMA.
__global__ void __launch_bounds__(256) k_gemm2(const float* __restrict__ B,
                                               const float* __restrict__ bias,
                                               int first) {
    __shared__ float As[8][129];
    __shared__ float Bs[8][128];
    const float* A = g_u;
    int tid = threadIdx.x;
    int tx = tid & 15, ty = tid >> 4;
    int row0 = blockIdx.x * 128;
    unsigned long long acc[8][4];
#pragma unroll
    for (int i = 0; i < 8; i++)
#pragma unroll
        for (int j = 0; j < 4; j++) acc[i][j] = 0ull;

    for (int kk = 0; kk < H2; kk += 8) {
        {
            int m = tid >> 1, k0 = (tid & 1) * 4;
            int r = row0 + m;
            float4 av = (r < N_NODES) ? __ldg((const float4*)&A[(size_t)r * H2 + kk + k0])
                                      : make_float4(0.f, 0.f, 0.f, 0.f);
            As[k0 + 0][m] = av.x; As[k0 + 1][m] = av.y;
            As[k0 + 2][m] = av.z; As[k0 + 3][m] = av.w;
        }
        {
            int k = tid >> 5, n4 = tid & 31;
            *(float4*)&Bs[k][n4 * 4] = __ldg((const float4*)&B[(kk + k) * HDIM + n4 * 4]);
        }
        __syncthreads();
#pragma unroll
        for (int k = 0; k < 8; k++) {
            unsigned long long bv[4];
            bv[0] = *(const unsigned long long*)&Bs[k][tx * 4];
            bv[1] = *(const unsigned long long*)&Bs[k][tx * 4 + 2];
            bv[2] = *(const unsigned long long*)&Bs[k][64 + tx * 4];
            bv[3] = *(const unsigned long long*)&Bs[k][64 + tx * 4 + 2];
#pragma unroll
            for (int i = 0; i < 8; i++) {
                unsigned long long a2 = dup2(As[k][ty * 8 + i]);
#pragma unroll
                for (int j = 0; j < 4; j++) acc[i][j] = fma2(a2, bv[j], acc[i][j]);
            }
        }
        __syncthreads();
    }
    float4 bia0 = __ldg((const float4*)&bias[tx * 4]);
    float4 bia1 = __ldg((const float4*)&bias[64 + tx * 4]);
#pragma unroll
    for (int i = 0; i < 8; i++) {
        int r = row0 + ty * 8 + i;
        if (r < N_NODES) {
            float2 p;
            float4 y0, y1;
            p = unpack2(acc[i][0]); y0.x = p.x + bia0.x; y0.y = p.y + bia0.y;
            p = unpack2(acc[i][1]); y0.z = p.x + bia0.z; y0.w = p.y + bia0.w;
            p = unpack2(acc[i][2]); y1.x = p.x + bia1.x; y1.y = p.y + bia1.y;
            p = unpack2(acc[i][3]); y1.z = p.x + bia1.z; y1.w = p.y + bia1.w;
            float* hp = &g_h[(size_t)r * HDIM];
            if (first) {
                *(float4*)&hp[tx * 4] = y0;
                *(float4*)&hp[64 + tx * 4] = y1;
            } else {
                float4 h0 = *(float4*)&hp[tx * 4];
                float4 h1 = *(float4*)&hp[64 + tx * 4];
                h0.x += y0.x; h0.y += y0.y; h0.z += y0.z; h0.w += y0.w;
                h1.x += y1.x; h1.y += y1.y; h1.z += y1.z; h1.w += y1.w;
                *(float4*)&hp[tx * 4] = h0;
                *(float4*)&hp[64 + tx * 4] = h1;
            }
        }
    }
}

// ---------------- global mean pool (deterministic, batch is sorted) ----------
__global__ void k_pool(float* __restrict__ out) {
    int g = blockIdx.x, c = threadIdx.x;
    int s = g_gptr[g], e = g_gptr[g + 1];
    float acc = 0.f;
    for (int i = s; i < e; i++) acc += g_z[(size_t)i * HDIM + c];
    out[g * HDIM + c] = (e > s) ? acc / (float)(e - s) : 0.f;
}

// ---------------- launch ------------------------------------------------------
extern "C" void kernel_launch(void* const* d_in, const int* in_sizes, int n_in,
                              void* d_out, int out_size) {
    (void)in_sizes; (void)n_in; (void)out_size;
    const float* x     = (const float*)d_in[0];
    const int*   ei    = (const int*)d_in[1];
    const float* eattr = (const float*)d_in[2];
    const int*   batch = (const int*)d_in[3];
    const float* encW  = (const float*)d_in[4];
    const float* encb  = (const float*)d_in[5];
    const float* eW    = (const float*)d_in[6];
    const float* eb    = (const float*)d_in[7];
    const float* lng   = (const float*)d_in[8];
    const float* lnb   = (const float*)d_in[9];
    const float* W1    = (const float*)d_in[10];
    const float* b1    = (const float*)d_in[11];
    const float* mg    = (const float*)d_in[12];
    const float* mb    = (const float*)d_in[13];
    const float* W2    = (const float*)d_in[14];
    const float* b2    = (const float*)d_in[15];
    const float* tptr  = (const float*)d_in[16];
    float* out = (float*)d_out;

    const int NWBLK = (N_NODES * 32 + 255) / 256;  // warp-per-node kernels

    // CSR + graph ranges (fast multi-block scan)
    k_zero<<<(N_NODES + 256) / 256, 256>>>();
    k_hist_dst<<<(N_EDGES + 255) / 256, 256>>>(ei);
    k_hist_batch<<<(N_NODES + 255) / 256, 256>>>(batch);
    k_scan1<<<SCAN_BLKS, 1024>>>();
    k_scan2<<<1, 1024>>>();
    k_scan3<<<SCAN_BLKS, 1024>>>();
    k_scatter<<<(N_EDGES + 255) / 256, 256>>>(ei, eattr);

    // node encoder
    k_encode<<<NWBLK, 256>>>(x, encW, encb);

    // layers
    for (int i = 0; i < NLAYERS; i++) {
        if (i > 0) k_lnrelu<<<NWBLK, 256>>>(lng + (size_t)i * HDIM, lnb + (size_t)i * HDIM);
        k_edge<<<NWBLK, 256>>>(eW, eb, tptr, i, (i > 0) ? 1 : 0);
        k_gemm1<<<(N_NODES + 63) / 64, 256>>>(W1 + (size_t)i * HDIM * H2,
                                              b1 + (size_t)i * H2,
                                              mg + (size_t)i * H2,
                                              mb + (size_t)i * H2);
        k_gemm2<<<(N_NODES + 127) / 128, 256>>>(W2 + (size_t)i * H2 * HDIM,
                                                b2 + (size_t)i * HDIM,
                                                (i == 0) ? 1 : 0);
    }

    // final norm (layer-0 params) + pool
    k_lnrelu<<<NWBLK, 256>>>(lng, lnb);
    k_pool<<<NGRAPH, HDIM>>>(out);
}

// round 12
// speedup vs baseline: 19.8140x; 1.1013x over previous
#include <cuda_runtime.h>
#include <cuda_bf16.h>
#include <cstdint>

#define N_NODES 50000
#define N_EDGES 500000
#define HDIM    128
#define H2      256
#define NLAYERS 4
#define NGRAPH  1000
#define MEPS    1e-7f
#define LNEPS   1e-5f
#define SCAN_BLKS 49

// ---------------- scratch ----------------------------------------------------
__device__ float  g_h[(size_t)N_NODES * HDIM];
__device__ float  g_z[(size_t)N_NODES * HDIM];
__device__ float  g_o[(size_t)N_NODES * HDIM];
__device__ float  g_u[(size_t)N_NODES * H2];
__device__ int    g_cnt[N_NODES + 1];
__device__ int    g_ptr[N_NODES + 1];
__device__ int    g_cur[N_NODES];
__device__ int    g_ssrc[N_EDGES];
__device__ float4 g_sattr[N_EDGES];
__device__ int    g_gcnt[NGRAPH + 1];
__device__ int    g_gptr[NGRAPH + 1];
__device__ int    g_bsum[64];
__device__ int    g_boff[64];

// ---------------- f32x2 helpers -----------------------------------------------
__device__ __forceinline__ unsigned long long fma2(unsigned long long a,
                                                   unsigned long long b,
                                                   unsigned long long c) {
    unsigned long long d;
    asm("fma.rn.f32x2 %0, %1, %2, %3;" : "=l"(d) : "l"(a), "l"(b), "l"(c));
    return d;
}
__device__ __forceinline__ unsigned long long dup2(float a) {
    unsigned long long d;
    asm("mov.b64 %0, {%1, %1};" : "=l"(d) : "f"(a));
    return d;
}
__device__ __forceinline__ float2 unpack2(unsigned long long v) {
    float2 r;
    asm("mov.b64 {%0, %1}, %2;" : "=f"(r.x), "=f"(r.y) : "l"(v));
    return r;
}

// ---------------- prep --------------------------------------------------------
__global__ void k_zero() {
    int i = blockIdx.x * blockDim.x + threadIdx.x;
    if (i <= N_NODES) g_cnt[i] = 0;
    if (i <= NGRAPH) g_gcnt[i] = 0;
}
__global__ void k_hist_dst(const int* __restrict__ ei) {
    int e = blockIdx.x * blockDim.x + threadIdx.x;
    if (e < N_EDGES) atomicAdd(&g_cnt[ei[N_EDGES + e]], 1);
}
__global__ void k_hist_batch(const int* __restrict__ batch) {
    int i = blockIdx.x * blockDim.x + threadIdx.x;
    if (i < N_NODES) atomicAdd(&g_gcnt[batch[i]], 1);
}
__device__ __forceinline__ int blk_scan(int v, int* ws) {
    int lane = threadIdx.x & 31, w = threadIdx.x >> 5;
    int val = v;
#pragma unroll
    for (int o = 1; o < 32; o <<= 1) { int u = __shfl_up_sync(0xffffffffu, val, o); if (lane >= o) val += u; }
    if (lane == 31) ws[w] = val;
    __syncthreads();
    if (w == 0) {
        int s = ws[lane];
#pragma unroll
        for (int o = 1; o < 32; o <<= 1) { int u = __shfl_up_sync(0xffffffffu, s, o); if (lane >= o) s += u; }
        ws[lane] = s;
    }
    __syncthreads();
    return val + (w ? ws[w - 1] : 0);
}
__global__ void k_scan1() {
    __shared__ int ws[32];
    int i = blockIdx.x * 1024 + threadIdx.x;
    int v = (i < N_NODES) ? g_cnt[i] : 0;
    int incl = blk_scan(v, ws);
    if (i < N_NODES) g_ptr[i] = incl - v;
    if (threadIdx.x == 1023) g_bsum[blockIdx.x] = incl;
}
__global__ void k_scan2() {
    __shared__ int ws[32];
    int t = threadIdx.x;
    int v = (t < SCAN_BLKS) ? g_bsum[t] : 0;
    int incl = blk_scan(v, ws);
    if (t < SCAN_BLKS) g_boff[t] = incl - v;
    __syncthreads();
    int gv = (t < NGRAPH) ? g_gcnt[t] : 0;
    int gincl = blk_scan(gv, ws);
    if (t < NGRAPH) g_gptr[t] = gincl - gv;
    if (t == 0) g_gptr[NGRAPH] = N_NODES;
}
__global__ void k_scan3() {
    int i = blockIdx.x * 1024 + threadIdx.x;
    if (i < N_NODES) {
        int p = g_ptr[i] + g_boff[blockIdx.x];
        g_ptr[i] = p;
        g_cur[i] = p;
    }
    if (i == 0) g_ptr[N_NODES] = N_EDGES;
}
__global__ void k_scatter(const int* __restrict__ ei, const float* __restrict__ ea) {
    int e = blockIdx.x * blockDim.x + threadIdx.x;
    if (e >= N_EDGES) return;
    int d = ei[N_EDGES + e];
    int pos = atomicAdd(&g_cur[d], 1);
    g_ssrc[pos] = ei[e];
    g_sattr[pos] = make_float4(ea[3 * e], ea[3 * e + 1], ea[3 * e + 2], 0.f);
}

// ---------------- node encoder ------------------------------------------------
__global__ void k_encode(const float* __restrict__ x, const float* __restrict__ W,
                         const float* __restrict__ b) {
    __shared__ float4 sW[9][32];
    __shared__ float4 sb[32];
    int tid = threadIdx.x;
    for (int i = tid; i < 9 * 32; i += blockDim.x)
        sW[i / 32][i % 32] = *(const float4*)&W[(i / 32) * HDIM + (i % 32) * 4];
    if (tid < 32) sb[tid] = *(const float4*)&b[tid * 4];
    __syncthreads();
    int gw = (blockIdx.x * blockDim.x + tid) >> 5;
    if (gw >= N_NODES) return;
    int lane = tid & 31;
    const float* xr = x + gw * 9;
    float xv[9];
#pragma unroll
    for (int k = 0; k < 9; k++) xv[k] = __ldg(&xr[k]);
    float4 acc = sb[lane];
#pragma unroll
    for (int k = 0; k < 9; k++) {
        float4 w = sW[k][lane];
        acc.x += xv[k] * w.x; acc.y += xv[k] * w.y;
        acc.z += xv[k] * w.z; acc.w += xv[k] * w.w;
    }
    ((float4*)g_h)[gw * 32 + lane] = acc;
}

// ---------------- edge softmax-aggregation (warp per node) --------------------
__global__ void __launch_bounds__(256) k_edge(const float* __restrict__ eW,
                                              const float* __restrict__ eb,
                                              const float* __restrict__ tall,
                                              int layer, int use_z) {
    __shared__ float4 sw[4][32];
    int tid = threadIdx.x;
    if (tid < 32) {
        sw[0][tid] = *(const float4*)&eW[0 * HDIM + tid * 4];
        sw[1][tid] = *(const float4*)&eW[1 * HDIM + tid * 4];
        sw[2][tid] = *(const float4*)&eW[2 * HDIM + tid * 4];
        sw[3][tid] = *(const float4*)&eb[tid * 4];
    }
    __syncthreads();
    int gw = (blockIdx.x * blockDim.x + tid) >> 5;
    if (gw >= N_NODES) return;
    int lane = tid & 31;
    const float4* zp = (const float4*)(use_z ? g_z : g_h);
    float tv = __ldg(&tall[layer]);
    int j0 = __ldg(&g_ptr[gw]), j1 = __ldg(&g_ptr[gw + 1]);
    float4 w0 = sw[0][lane], w1 = sw[1][lane], w2 = sw[2][lane], wb = sw[3][lane];
    float4 den = make_float4(0.f, 0.f, 0.f, 0.f);
    float4 num = make_float4(0.f, 0.f, 0.f, 0.f);
    for (int j = j0; j < j1; j++) {
        int s = __ldg(&g_ssrc[j]);
        float4 a = __ldg(&g_sattr[j]);
        float4 hv = __ldg(&zp[s * 32 + lane]);
        float m, e;
        m = fmaxf(hv.x + wb.x + a.x * w0.x + a.y * w1.x + a.z * w2.x, 0.f) + MEPS;
        e = __expf(tv * m); den.x += e; num.x += e * m;
        m = fmaxf(hv.y + wb.y + a.x * w0.y + a.y * w1.y + a.z * w2.y, 0.f) + MEPS;
        e = __expf(tv * m); den.y += e; num.y += e * m;
        m = fmaxf(hv.z + wb.z + a.x * w0.z + a.y * w1.z + a.z * w2.z, 0.f) + MEPS;
        e = __expf(tv * m); den.z += e; num.z += e * m;
        m = fmaxf(hv.w + wb.w + a.x * w0.w + a.y * w1.w + a.z * w2.w, 0.f) + MEPS;
        e = __expf(tv * m); den.w += e; num.w += e * m;
    }
    float4 hz = zp[gw * 32 + lane];
    float4 o;
    if (j1 > j0) {
        o.x = num.x / den.x + hz.x;
        o.y = num.y / den.y + hz.y;
        o.z = num.z / den.z + hz.z;
        o.w = num.w / den.w + hz.w;
    } else {
        o = hz;
    }
    ((float4*)g_o)[gw * 32 + lane] = o;
}

// ---------------- GEMM1: u = relu(LN(g_o @ W1 + b1)) --------------------------
// BM=64, BN=256, BK=16, double-buffered, 256 thr, 8x8/thread, f32x2.
__global__ void __launch_bounds__(256) k_gemm1(const float* __restrict__ B,
                                               const float* __restrict__ bias,
                                               const float* __restrict__ lg,
                                               const float* __restrict__ lb) {
    __shared__ float As[2][16][65];
    __shared__ float Bs[2][16][256];
    int tid = threadIdx.x;
    int tx = tid & 31, ty = tid >> 5;
    int row0 = blockIdx.x * 64;
    int am = tid >> 2, ak = (tid & 3) * 4;     // A: 1 float4/thread
    int bn4 = tid & 63, bk0 = tid >> 6;        // B: 4 float4/thread (bk0+4l)
    unsigned long long acc[8][4];
#pragma unroll
    for (int i = 0; i < 8; i++)
#pragma unroll
        for (int j = 0; j < 4; j++) acc[i][j] = 0ull;

    {   // preload chunk 0
        int r = row0 + am;
        float4 va = (r < N_NODES) ? *(const float4*)&g_o[(size_t)r * HDIM + ak]
                                  : make_float4(0.f, 0.f, 0.f, 0.f);
        As[0][ak + 0][am] = va.x; As[0][ak + 1][am] = va.y;
        As[0][ak + 2][am] = va.z; As[0][ak + 3][am] = va.w;
#pragma unroll
        for (int l = 0; l < 4; l++) {
            int bk = bk0 + l * 4;
            *(float4*)&Bs[0][bk][bn4 * 4] = __ldg((const float4*)&B[(size_t)bk * H2 + bn4 * 4]);
        }
    }
    __syncthreads();

    for (int it = 0; it < 8; it++) {
        int cur = it & 1;
        float4 va;
        float4 vb[4];
        if (it < 7) {
            int kkn = (it + 1) * 16;
            int r = row0 + am;
            va = (r < N_NODES) ? *(const float4*)&g_o[(size_t)r * HDIM + kkn + ak]
                               : make_float4(0.f, 0.f, 0.f, 0.f);
#pragma unroll
            for (int l = 0; l < 4; l++) {
                int bk = bk0 + l * 4;
                vb[l] = __ldg((const float4*)&B[(size_t)(kkn + bk) * H2 + bn4 * 4]);
            }
        }
#pragma unroll
        for (int k = 0; k < 16; k++) {
            unsigned long long bv[4];
            bv[0] = *(const unsigned long long*)&Bs[cur][k][tx * 4];
            bv[1] = *(const unsigned long long*)&Bs[cur][k][tx * 4 + 2];
            bv[2] = *(const unsigned long long*)&Bs[cur][k][128 + tx * 4];
            bv[3] = *(const unsigned long long*)&Bs[cur][k][128 + tx * 4 + 2];
#pragma unroll
            for (int i = 0; i < 8; i++) {
                unsigned long long a2 = dup2(As[cur][k][ty * 8 + i]);
#pragma unroll
                for (int j = 0; j < 4; j++) acc[i][j] = fma2(a2, bv[j], acc[i][j]);
            }
        }
        if (it < 7) {
            int nb = cur ^ 1;
            As[nb][ak + 0][am] = va.x; As[nb][ak + 1][am] = va.y;
            As[nb][ak + 2][am] = va.z; As[nb][ak + 3][am] = va.w;
#pragma unroll
            for (int l = 0; l < 4; l++) {
                int bk = bk0 + l * 4;
                *(float4*)&Bs[nb][bk][bn4 * 4] = vb[l];
            }
            __syncthreads();
        }
    }

    float4 bia0 = __ldg((const float4*)&bias[tx * 4]);
    float4 bia1 = __ldg((const float4*)&bias[128 + tx * 4]);
    float4 gv0 = __ldg((const float4*)&lg[tx * 4]);
    float4 gv1 = __ldg((const float4*)&lg[128 + tx * 4]);
    float4 bv0 = __ldg((const float4*)&lb[tx * 4]);
    float4 bv1 = __ldg((const float4*)&lb[128 + tx * 4]);
#pragma unroll
    for (int i = 0; i < 8; i++) {
        float v[8];
        float2 p;
        p = unpack2(acc[i][0]); v[0] = p.x + bia0.x; v[1] = p.y + bia0.y;
        p = unpack2(acc[i][1]); v[2] = p.x + bia0.z; v[3] = p.y + bia0.w;
        p = unpack2(acc[i][2]); v[4] = p.x + bia1.x; v[5] = p.y + bia1.y;
        p = unpack2(acc[i][3]); v[6] = p.x + bia1.z; v[7] = p.y + bia1.w;
        float s = 0.f;
#pragma unroll
        for (int j = 0; j < 8; j++) s += v[j];
#pragma unroll
        for (int o = 16; o > 0; o >>= 1) s += __shfl_xor_sync(0xffffffffu, s, o);
        float mean = s * (1.f / 256.f);
        float q = 0.f;
#pragma unroll
        for (int j = 0; j < 8; j++) { float d = v[j] - mean; q += d * d; }
#pragma unroll
        for (int o = 16; o > 0; o >>= 1) q += __shfl_xor_sync(0xffffffffu, q, o);
        float rstd = rsqrtf(q * (1.f / 256.f) + LNEPS);
        int r = row0 + ty * 8 + i;
        if (r < N_NODES) {
            float4 o0, o1;
            o0.x = fmaxf((v[0] - mean) * rstd * gv0.x + bv0.x, 0.f);
            o0.y = fmaxf((v[1] - mean) * rstd * gv0.y + bv0.y, 0.f);
            o0.z = fmaxf((v[2] - mean) * rstd * gv0.z + bv0.z, 0.f);
            o0.w = fmaxf((v[3] - mean) * rstd * gv0.w + bv0.w, 0.f);
            o1.x = fmaxf((v[4] - mean) * rstd * gv1.x + bv1.x, 0.f);
            o1.y = fmaxf((v[5] - mean) * rstd * gv1.y + bv1.y, 0.f);
            o1.z = fmaxf((v[6] - mean) * rstd * gv1.z + bv1.z, 0.f);
            o1.w = fmaxf((v[7] - mean) * rstd * gv1.w + bv1.w, 0.f);
            *(float4*)&g_u[(size_t)r * H2 + tx * 4] = o0;
            *(float4*)&g_u[(size_t)r * H2 + 128 + tx * 4] = o1;
        }
    }
}

// ---------------- GEMM2 + fused next-layer LN ---------------------------------
// BM=128, BN=128, BK=16, double-buffered; writes g_h (raw) and g_z = relu(LN(h)).
__global__ void __launch_bounds__(256) k_gemm2(const float* __restrict__ B,
                                               const float* __restrict__ bias,
                                               const float* __restrict__ nlg,
                                               const float* __restrict__ nlb,
                                               int first) {
    __shared__ float As[2][16][129];
    __shared__ float Bs[2][16][128];
    int tid = threadIdx.x;
    int tx = tid & 15, ty = tid >> 4;
    int row0 = blockIdx.x * 128;
    unsigned long long acc[8][4];
#pragma unroll
    for (int i = 0; i < 8; i++)
#pragma unroll
        for (int j = 0; j < 4; j++) acc[i][j] = 0ull;

    // A: 2 float4/thread; B: 2 float4/thread
#pragma unroll
    for (int l = 0; l < 2; l++) {   // preload chunk 0
        int idx = tid + l * 256;
        int m = idx >> 2, k4 = (idx & 3) * 4;
        int r = row0 + m;
        float4 va = (r < N_NODES) ? *(const float4*)&g_u[(size_t)r * H2 + k4]
                                  : make_float4(0.f, 0.f, 0.f, 0.f);
        As[0][k4 + 0][m] = va.x; As[0][k4 + 1][m] = va.y;
        As[0][k4 + 2][m] = va.z; As[0][k4 + 3][m] = va.w;
        int bk = idx >> 5, bn4 = idx & 31;
        *(float4*)&Bs[0][bk][bn4 * 4] = __ldg((const float4*)&B[(size_t)bk * HDIM + bn4 * 4]);
    }
    __syncthreads();

    for (int it = 0; it < 16; it++) {
        int cur = it & 1;
        float4 va[2], vb[2];
        if (it < 15) {
            int kkn = (it + 1) * 16;
#pragma unroll
            for (int l = 0; l < 2; l++) {
                int idx = tid + l * 256;
                int m = idx >> 2, k4 = (idx & 3) * 4;
                int r = row0 + m;
                va[l] = (r < N_NODES) ? *(const float4*)&g_u[(size_t)r * H2 + kkn + k4]
                                      : make_float4(0.f, 0.f, 0.f, 0.f);
                int bk = idx >> 5, bn4 = idx & 31;
                vb[l] = __ldg((const float4*)&B[(size_t)(kkn + bk) * HDIM + bn4 * 4]);
            }
        }
#pragma unroll
        for (int k = 0; k < 16; k++) {
            unsigned long long bv[4];
            bv[0] = *(const unsigned long long*)&Bs[cur][k][tx * 4];
            bv[1] = *(const unsigned long long*)&Bs[cur][k][tx * 4 + 2];
            bv[2] = *(const unsigned long long*)&Bs[cur][k][64 + tx * 4];
            bv[3] = *(const unsigned long long*)&Bs[cur][k][64 + tx * 4 + 2];
#pragma unroll
            for (int i = 0; i < 8; i++) {
                unsigned long long a2 = dup2(As[cur][k][ty * 8 + i]);
#pragma unroll
                for (int j = 0; j < 4; j++) acc[i][j] = fma2(a2, bv[j], acc[i][j]);
            }
        }
        if (it < 15) {
            int nb = cur ^ 1;
#pragma unroll
            for (int l = 0; l < 2; l++) {
                int idx = tid + l * 256;
                int m = idx >> 2, k4 = (idx & 3) * 4;
                As[nb][k4 + 0][m] = va[l].x; As[nb][k4 + 1][m] = va[l].y;
                As[nb][k4 + 2][m] = va[l].z; As[nb][k4 + 3][m] = va[l].w;
                int bk = idx >> 5, bn4 = idx & 31;
                *(float4*)&Bs[nb][bk][bn4 * 4] = vb[l];
            }
            __syncthreads();
        }
    }

    float4 bia0 = __ldg((const float4*)&bias[tx * 4]);
    float4 bia1 = __ldg((const float4*)&bias[64 + tx * 4]);
    float4 gg0 = __ldg((const float4*)&nlg[tx * 4]);
    float4 gg1 = __ldg((const float4*)&nlg[64 + tx * 4]);
    float4 cb0 = __ldg((const float4*)&nlb[tx * 4]);
    float4 cb1 = __ldg((const float4*)&nlb[64 + tx * 4]);
#pragma unroll
    for (int i = 0; i < 8; i++) {
        int r = row0 + ty * 8 + i;       // uniform across the 16-lane tx group
        bool ok = (r < N_NODES);
        float2 p;
        float4 y0, y1;
        p = unpack2(acc[i][0]); y0.x = p.x + bia0.x; y0.y = p.y + bia0.y;
        p = unpack2(acc[i][1]); y0.z = p.x + bia0.z; y0.w = p.y + bia0.w;
        p = unpack2(acc[i][2]); y1.x = p.x + bia1.x; y1.y = p.y + bia1.y;
        p = unpack2(acc[i][3]); y1.z = p.x + bia1.z; y1.w = p.y + bia1.w;
        float* hp = &g_h[(size_t)r * HDIM];
        if (!first && ok) {
            float4 h0 = *(float4*)&hp[tx * 4];
            float4 h1 = *(float4*)&hp[64 + tx * 4];
            y0.x += h0.x; y0.y += h0.y; y0.z += h0.z; y0.w += h0.w;
            y1.x += h1.x; y1.y += h1.y; y1.z += h1.z; y1.w += h1.w;
        }
        if (ok) {
            *(float4*)&hp[tx * 4] = y0;
            *(float4*)&hp[64 + tx * 4] = y1;
        }
        // fused LN over 128 cols (16-lane group reduction; offsets 1,2,4,8 stay in group)
        float s = y0.x + y0.y + y0.z + y0.w + y1.x + y1.y + y1.z + y1.w;
#pragma unroll
        for (int o = 8; o > 0; o >>= 1) s += __shfl_xor_sync(0xffffffffu, s, o);
        float mean = s * (1.f / 128.f);
        float q = 0.f;
        q += (y0.x - mean) * (y0.x - mean) + (y0.y - mean) * (y0.y - mean);
        q += (y0.z - mean) * (y0.z - mean) + (y0.w - mean) * (y0.w - mean);
        q += (y1.x - mean) * (y1.x - mean) + (y1.y - mean) * (y1.y - mean);
        q += (y1.z - mean) * (y1.z - mean) + (y1.w - mean) * (y1.w - mean);
#pragma unroll
        for (int o = 8; o > 0; o >>= 1) q += __shfl_xor_sync(0xffffffffu, q, o);
        float rstd = rsqrtf(q * (1.f / 128.f) + LNEPS);
        if (ok) {
            float4 z0, z1;
            z0.x = fmaxf((y0.x - mean) * rstd * gg0.x + cb0.x, 0.f);
            z0.y = fmaxf((y0.y - mean) * rstd * gg0.y + cb0.y, 0.f);
            z0.z = fmaxf((y0.z - mean) * rstd * gg0.z + cb0.z, 0.f);
            z0.w = fmaxf((y0.w - mean) * rstd * gg0.w + cb0.w, 0.f);
            z1.x = fmaxf((y1.x - mean) * rstd * gg1.x + cb1.x, 0.f);
            z1.y = fmaxf((y1.y - mean) * rstd * gg1.y + cb1.y, 0.f);
            z1.z = fmaxf((y1.z - mean) * rstd * gg1.z + cb1.z, 0.f);
            z1.w = fmaxf((y1.w - mean) * rstd * gg1.w + cb1.w, 0.f);
            float* zp = &g_z[(size_t)r * HDIM];
            *(float4*)&zp[tx * 4] = z0;
            *(float4*)&zp[64 + tx * 4] = z1;
        }
    }
}

// ---------------- mean pool ---------------------------------------------------
__global__ void k_pool(float* __restrict__ out) {
    int g = blockIdx.x, c = threadIdx.x;
    int s = g_gptr[g], e = g_gptr[g + 1];
    float acc = 0.f;
    for (int i = s; i < e; i++) acc += g_z[(size_t)i * HDIM + c];
    out[g * HDIM + c] = (e > s) ? acc / (float)(e - s) : 0.f;
}

// ---------------- launch ------------------------------------------------------
extern "C" void kernel_launch(void* const* d_in, const int* in_sizes, int n_in,
                              void* d_out, int out_size) {
    (void)in_sizes; (void)n_in; (void)out_size;
    const float* x     = (const float*)d_in[0];
    const int*   ei    = (const int*)d_in[1];
    const float* eattr = (const float*)d_in[2];
    const int*   batch = (const int*)d_in[3];
    const float* encW  = (const float*)d_in[4];
    const float* encb  = (const float*)d_in[5];
    const float* eW    = (const float*)d_in[6];
    const float* eb    = (const float*)d_in[7];
    const float* lng   = (const float*)d_in[8];
    const float* lnb   = (const float*)d_in[9];
    const float* W1    = (const float*)d_in[10];
    const float* b1    = (const float*)d_in[11];
    const float* mg    = (const float*)d_in[12];
    const float* mb    = (const float*)d_in[13];
    const float* W2    = (const float*)d_in[14];
    const float* b2    = (const float*)d_in[15];
    const float* tptr  = (const float*)d_in[16];
    float* out = (float*)d_out;

    const int NWBLK = (N_NODES * 32 + 255) / 256;

    k_zero<<<(N_NODES + 256) / 256, 256>>>();
    k_hist_dst<<<(N_EDGES + 255) / 256, 256>>>(ei);
    k_hist_batch<<<(N_NODES + 255) / 256, 256>>>(batch);
    k_scan1<<<SCAN_BLKS, 1024>>>();
    k_scan2<<<1, 1024>>>();
    k_scan3<<<SCAN_BLKS, 1024>>>();
    k_scatter<<<(N_EDGES + 255) / 256, 256>>>(ei, eattr);

    k_encode<<<NWBLK, 256>>>(x, encW, encb);

    for (int i = 0; i < NLAYERS; i++) {
        // layer 0 edge reads raw h; later layers read z (written by fused gemm2 LN)
        k_edge<<<NWBLK, 256>>>(eW, eb, tptr, i, (i > 0) ? 1 : 0);
        k_gemm1<<<(N_NODES + 63) / 64, 256>>>(W1 + (size_t)i * HDIM * H2,
                                              b1 + (size_t)i * H2,
                                              mg + (size_t)i * H2,
                                              mb + (size_t)i * H2);
        // fuse NEXT layer's pre-norm (or the final layer-0 norm after layer 3)
        int nl = (i + 1 < NLAYERS) ? (i + 1) : 0;
        k_gemm2<<<(N_NODES + 127) / 128, 256>>>(W2 + (size_t)i * H2 * HDIM,
                                                b2 + (size_t)i * HDIM,
                                                lng + (size_t)nl * HDIM,
                                                lnb + (size_t)nl * HDIM,
                                                (i == 0) ? 1 : 0);
    }

    k_pool<<<NGRAPH, HDIM>>>(out);
}